// round 10
// baseline (speedup 1.0000x reference)
#include <cuda_runtime.h>
#include <cuda_fp16.h>

#define NN 50000
#define EE 800000
#define HHD 4
#define HC 128
#define FIN 64
#define SCAN_B 512
#define SCAN_GRID ((NN + SCAN_B - 1) / SCAN_B)   // 98

// ---------------- scratch (device globals; no allocation allowed) ----------
__device__ __align__(16) int      g_src[EE];
__device__ __align__(16) int      g_dst[EE];
__device__ __align__(16) int      g_csr_src[EE];
__device__ __align__(16) int      g_deg[NN];
__device__ __align__(16) int      g_off[NN];
__device__ __align__(16) int      g_cursor[NN];
__device__ __align__(16) unsigned g_h2[NN * 64];    // h as half2 pairs
__device__ __align__(16) float    g_resid[NN * HC]; // x @ res_w + res_b (fp32)
__device__ __align__(16) float    g_asrc[NN * HHD];
__device__ __align__(16) float    g_adst[NN * HHD];
__device__ int g_is64;
__device__ int g_gbase;                             // scan base allocator

// ---------------- helpers ---------------------------------------------------
__device__ __forceinline__ float lrelu(float x) { return x >= 0.f ? x : 0.2f * x; }
__device__ __forceinline__ int clampi(int v) {
    return v < 0 ? 0 : (v >= NN ? NN - 1 : v);
}
__device__ __forceinline__ unsigned f2tf(float f) {
    unsigned u;
    asm("cvt.rna.tf32.f32 %0, %1;" : "=r"(u) : "f"(f));
    return u;
}
__device__ __forceinline__ void mma_tf32(float* d, const unsigned* a,
                                         const unsigned* b) {
    asm volatile(
        "mma.sync.aligned.m16n8k8.row.col.f32.tf32.tf32.f32 "
        "{%0,%1,%2,%3}, {%4,%5,%6,%7}, {%8,%9}, {%0,%1,%2,%3};"
        : "+f"(d[0]), "+f"(d[1]), "+f"(d[2]), "+f"(d[3])
        : "r"(a[0]), "r"(a[1]), "r"(a[2]), "r"(a[3]), "r"(b[0]), "r"(b[1]));
}

// ---------------- edge-prep chain -------------------------------------------

// zero degree counters + base allocator + dtype detection
__global__ void k_zerodeg(const int* __restrict__ p) {
    int i = blockIdx.x * blockDim.x + threadIdx.x;
    if (i < NN) g_deg[i] = 0;
    if (i == 0) {
        g_gbase = 0;
        int ok64 = 1;
#pragma unroll
        for (int t = 0; t < 8; t++) {
            if (p[2 * t + 1] != 0) ok64 = 0;
            unsigned lo = (unsigned)p[2 * t];
            if (lo >= NN) ok64 = 0;
        }
        g_is64 = ok64;
    }
}

__global__ void k_convert(const int* __restrict__ p) {
    int i = blockIdx.x * blockDim.x + threadIdx.x;
    if (i >= EE) return;
    int s, d;
    if (g_is64) {
        s = ((const int2*)p)[i].x;        // int64 low word
        d = ((const int2*)p)[EE + i].x;
    } else {
        s = p[i];
        d = p[EE + i];
    }
    s = clampi(s); d = clampi(d);
    g_src[i] = s;
    g_dst[i] = d;
    atomicAdd(&g_deg[d], 1);
}

// one-pass scan: block-local exclusive scan + atomic base claim.
// (Global slice order is arbitrary; each node just needs a disjoint slice.)
__global__ void __launch_bounds__(SCAN_B) k_scan() {
    __shared__ int wsm[16];
    __shared__ int base;
    const int tid = threadIdx.x, lane = tid & 31, wid = tid >> 5;
    int idx = blockIdx.x * SCAN_B + tid;
    int v = (idx < NN) ? g_deg[idx] : 0;
    int xi = v;
#pragma unroll
    for (int o = 1; o < 32; o <<= 1) {
        int y = __shfl_up_sync(0xffffffffu, xi, o);
        if (lane >= o) xi += y;
    }
    if (lane == 31) wsm[wid] = xi;
    __syncthreads();
    if (wid == 0 && lane < 16) {
        int t = wsm[lane];
#pragma unroll
        for (int o = 1; o < 16; o <<= 1) {
            int y = __shfl_up_sync(0x0000ffffu, t, o);
            if (lane >= o) t += y;
        }
        wsm[lane] = t;
    }
    __syncthreads();
    if (tid == 0) base = atomicAdd(&g_gbase, wsm[15]);
    __syncthreads();
    int woff = (wid == 0) ? 0 : wsm[wid - 1];
    if (idx < NN) {
        int o = base + woff + xi - v;
        g_off[idx] = o;
        g_cursor[idx] = o;
    }
}

__global__ void k_scatter() {
    int i = blockIdx.x * blockDim.x + threadIdx.x;
    if (i >= EE) return;
    int d = g_dst[i];
    int pos = atomicAdd(&g_cursor[d], 1);
    g_csr_src[pos] = g_src[i];
}

// ---------------- TF32 tensor-core GEMM + fused fold + att scalars -----------
// [NN x 64] @ [64 x 256]  (cols 0..127 -> g_h2 fp16, 128..255 -> g_resid+res_b)
#define SX 68
#define SW 264
#define GEMM_SMEM ((64 * SX + 64 * SW + 512) * 4)

__global__ void __launch_bounds__(256) k_gemm_mma(
        const float* __restrict__ x, const float* __restrict__ W,
        const float* __restrict__ res_w, const float* __restrict__ res_b,
        const float* __restrict__ att_src, const float* __restrict__ att_dst) {
    extern __shared__ unsigned sh[];
    unsigned* xs  = sh;                                // 64 x SX (tf32 bits)
    unsigned* ws  = sh + 64 * SX;                      // 64 x SW (tf32 bits)
    float*    was = (float*)(sh + 64 * SX + 64 * SW);  // 512 folded att weights

    const int tid  = threadIdx.x;
    const int row0 = blockIdx.x * 64;

    // fold attention weights from fp32 gmem (L2-hot): 2 outputs per thread
    {
        int o = tid;
#pragma unroll
        for (int rep = 0; rep < 2; rep++, o += 256) {
            int k = o >> 3, j = o & 7, p = j & 3;
            const float* att = (j < 4) ? att_src : att_dst;
            float s = 0.f;
#pragma unroll
            for (int c = 0; c < 32; c++)
                s += W[k * HC + p * 32 + c] * att[p * 32 + c];
            was[o] = s;
        }
    }
    for (int i = tid; i < FIN * 32; i += 256) {
        int k = i >> 5, q = i & 31;
        float4 w1 = ((const float4*)W)[k * 32 + q];
        float4 w2 = ((const float4*)res_w)[k * 32 + q];
        unsigned* p1 = &ws[k * SW + 4 * q];
        unsigned* p2 = &ws[k * SW + 128 + 4 * q];
        p1[0] = f2tf(w1.x); p1[1] = f2tf(w1.y); p1[2] = f2tf(w1.z); p1[3] = f2tf(w1.w);
        p2[0] = f2tf(w2.x); p2[1] = f2tf(w2.y); p2[2] = f2tf(w2.z); p2[3] = f2tf(w2.w);
    }
    for (int i = tid; i < 64 * 16; i += 256) {
        int r = i >> 4, q = i & 15;
        int row = row0 + r;
        float4 xv = (row < NN) ? ((const float4*)x)[row * 16 + q]
                               : make_float4(0.f, 0.f, 0.f, 0.f);
        unsigned* p = &xs[r * SX + 4 * q];
        p[0] = f2tf(xv.x); p[1] = f2tf(xv.y); p[2] = f2tf(xv.z); p[3] = f2tf(xv.w);
    }
    __syncthreads();

    const int warp = tid >> 5, lane = tid & 31;
    const int mw = warp >> 2, nw = warp & 3;
    const int grp = lane >> 2, tig = lane & 3;
    const int mbase = mw * 32, nbase = nw * 64;

    float acc[2][8][4];
#pragma unroll
    for (int mt = 0; mt < 2; mt++)
#pragma unroll
        for (int nt = 0; nt < 8; nt++)
#pragma unroll
            for (int e = 0; e < 4; e++) acc[mt][nt][e] = 0.f;

#pragma unroll
    for (int kt = 0; kt < 8; kt++) {
        const int k0 = kt * 8;
        unsigned afr[2][4], bfr[8][2];
#pragma unroll
        for (int mt = 0; mt < 2; mt++) {
            int base = (mbase + mt * 16 + grp) * SX + k0 + tig;
            afr[mt][0] = xs[base];
            afr[mt][1] = xs[base + 8 * SX];
            afr[mt][2] = xs[base + 4];
            afr[mt][3] = xs[base + 8 * SX + 4];
        }
#pragma unroll
        for (int nt = 0; nt < 8; nt++) {
            int bb = (k0 + tig) * SW + nbase + nt * 8 + grp;
            bfr[nt][0] = ws[bb];
            bfr[nt][1] = ws[bb + 4 * SW];
        }
#pragma unroll
        for (int mt = 0; mt < 2; mt++)
#pragma unroll
            for (int nt = 0; nt < 8; nt++)
                mma_tf32(acc[mt][nt], afr[mt], bfr[nt]);
    }

    // epilogue: nw 0,1 -> g_h2 (fp16) ; nw 2,3 -> g_resid (fp32, +res_b)
#pragma unroll
    for (int mt = 0; mt < 2; mt++) {
        int r0 = row0 + mbase + mt * 16 + grp;
#pragma unroll
        for (int nt = 0; nt < 8; nt++) {
            int col = nbase + nt * 8 + 2 * tig;
            float v00 = acc[mt][nt][0], v01 = acc[mt][nt][1];
            float v10 = acc[mt][nt][2], v11 = acc[mt][nt][3];
            if (nw < 2) {
                int cp = col >> 1;
                if (r0 < NN)
                    *(__half2*)&g_h2[r0 * 64 + cp] = __floats2half2_rn(v00, v01);
                if (r0 + 8 < NN)
                    *(__half2*)&g_h2[(r0 + 8) * 64 + cp] = __floats2half2_rn(v10, v11);
            } else {
                int cr = col - HC;
                float b0 = res_b[cr], b1 = res_b[cr + 1];
                if (r0 < NN)
                    *(float2*)&g_resid[r0 * HC + cr] = make_float2(v00 + b0, v01 + b1);
                if (r0 + 8 < NN)
                    *(float2*)&g_resid[(r0 + 8) * HC + cr] = make_float2(v10 + b0, v11 + b1);
            }
        }
    }

    // attention scalars from staged x tile (tf32) and folded weights
    {
        const int n = tid >> 2, p = tid & 3;
        float a = 0.f, b = 0.f;
#pragma unroll 16
        for (int k = 0; k < FIN; k++) {
            float xv = __uint_as_float(xs[n * SX + k]);
            a += xv * was[k * 8 + p];
            b += xv * was[k * 8 + 4 + p];
        }
        int node = row0 + n;
        if (node < NN) {
            g_asrc[node * HHD + p] = a;
            g_adst[node * HHD + p] = b;
        }
    }
}

// ---------------- fused aggregate + epilogue ---------------------------------
__global__ void __launch_bounds__(256) k_aggregate(
        const float* __restrict__ bias,
        const float* __restrict__ ln_g, const float* __restrict__ ln_b,
        float* __restrict__ out) {
    int node = (blockIdx.x * blockDim.x + threadIdx.x) >> 5;
    if (node >= NN) return;
    const int l  = threadIdx.x & 31;
    const int hh = l >> 3;

    const float ad = g_adst[node * HHD + hh];
    const int beg = g_off[node];
    const int n   = g_deg[node];

    float4 acc = make_float4(0.f, 0.f, 0.f, 0.f);
    float dsum = 0.f;

    for (int base = 0; base < n; base += 32) {
        int id = (base + l < n) ? g_csr_src[beg + base + l] : 0;
        int cnt = min(32, n - base);
#pragma unroll 4
        for (int j = 0; j < cnt; j++) {
            int s = __shfl_sync(0xffffffffu, id, j);
            float as = g_asrc[s * HHD + hh];
            float ex = __expf(lrelu(as + ad));
            uint2 hb = *(const uint2*)&g_h2[s * 64 + l * 2];
            float2 h01 = __half22float2(*(const __half2*)&hb.x);
            float2 h23 = __half22float2(*(const __half2*)&hb.y);
            acc.x += h01.x * ex; acc.y += h01.y * ex;
            acc.z += h23.x * ex; acc.w += h23.y * ex;
            dsum += ex;
        }
    }

    { // self-loop
        float as = g_asrc[node * HHD + hh];
        float ex = __expf(lrelu(as + ad));
        uint2 hb = *(const uint2*)&g_h2[node * 64 + l * 2];
        float2 h01 = __half22float2(*(const __half2*)&hb.x);
        float2 h23 = __half22float2(*(const __half2*)&hb.y);
        acc.x += h01.x * ex; acc.y += h01.y * ex;
        acc.z += h23.x * ex; acc.w += h23.y * ex;
        dsum += ex;
    }

    float inv = 1.f / dsum;
    float4 bv = *(const float4*)&bias[l * 4];
    float4 rv = *(const float4*)&g_resid[node * HC + l * 4];
    float4 v;
    v.x = acc.x * inv + bv.x;  v.y = acc.y * inv + bv.y;
    v.z = acc.z * inv + bv.z;  v.w = acc.w * inv + bv.w;
    v.x = (v.x > 0.f) ? v.x : expm1f(v.x);
    v.y = (v.y > 0.f) ? v.y : expm1f(v.y);
    v.z = (v.z > 0.f) ? v.z : expm1f(v.z);
    v.w = (v.w > 0.f) ? v.w : expm1f(v.w);
    v.x += rv.x; v.y += rv.y; v.z += rv.z; v.w += rv.w;

    float s1 = v.x + v.y + v.z + v.w;
    float s2 = v.x * v.x + v.y * v.y + v.z * v.z + v.w * v.w;
#pragma unroll
    for (int o = 16; o > 0; o >>= 1) {
        s1 += __shfl_xor_sync(0xffffffffu, s1, o);
        s2 += __shfl_xor_sync(0xffffffffu, s2, o);
    }
    float mu  = s1 * (1.f / 128.f);
    float var = s2 * (1.f / 128.f) - mu * mu;
    float r = rsqrtf(var + 1e-5f);

    float4 gv  = *(const float4*)&ln_g[l * 4];
    float4 bbv = *(const float4*)&ln_b[l * 4];
    float4 o4;
    o4.x = gv.x * (v.x - mu) * r + bbv.x;
    o4.y = gv.y * (v.y - mu) * r + bbv.y;
    o4.z = gv.z * (v.z - mu) * r + bbv.z;
    o4.w = gv.w * (v.w - mu) * r + bbv.w;
    *(float4*)&out[node * HC + l * 4] = o4;
}

// ---------------- launch -----------------------------------------------------
extern "C" void kernel_launch(void* const* d_in, const int* in_sizes, int n_in,
                              void* d_out, int out_size) {
    const float* x       = (const float*)d_in[0];
    const int*   ei      = (const int*)d_in[1];
    const float* W       = (const float*)d_in[2];
    const float* att_src = (const float*)d_in[3];
    const float* att_dst = (const float*)d_in[4];
    const float* bias    = (const float*)d_in[5];
    const float* res_w   = (const float*)d_in[6];
    const float* res_b   = (const float*)d_in[7];
    const float* ln_g    = (const float*)d_in[8];
    const float* ln_b    = (const float*)d_in[9];
    float*       out     = (float*)d_out;

    static bool init = false;
    if (!init) {
        cudaFuncSetAttribute(k_gemm_mma,
                             cudaFuncAttributeMaxDynamicSharedMemorySize, GEMM_SMEM);
        init = true;
    }

    k_zerodeg<<<(NN + 255) / 256, 256>>>(ei);
    k_convert<<<(EE + 255) / 256, 256>>>(ei);
    k_scan<<<SCAN_GRID, SCAN_B>>>();
    k_scatter<<<(EE + 255) / 256, 256>>>();

    k_gemm_mma<<<(NN + 63) / 64, 256, GEMM_SMEM>>>(x, W, res_w, res_b,
                                                   att_src, att_dst);

    k_aggregate<<<(NN * 32 + 255) / 256, 256>>>(bias, ln_g, ln_b, out);
}

// round 12
// speedup vs baseline: 1.2967x; 1.2967x over previous
#include <cuda_runtime.h>
#include <cuda_fp16.h>

#define NN 50000
#define EE 800000
#define HHD 4
#define HC 128
#define FIN 64
#define SCAN_B 512
#define SCAN_GRID ((NN + SCAN_B - 1) / SCAN_B)   // 98
#define ZG ((NN + 255) / 256)                    // 196 zero blocks
#define FOLD_BLOCKS 64                           // 512 outputs, warp per output

// ---------------- scratch (device globals; no allocation allowed) ----------
__device__ __align__(16) int      g_src[EE];
__device__ __align__(16) int      g_dst[EE];
__device__ __align__(16) int      g_csr_src[EE];
__device__ __align__(16) int      g_deg[NN];
__device__ __align__(16) int      g_off[NN];
__device__ __align__(16) int      g_cursor[NN];
__device__ __align__(16) unsigned g_h2[NN * 64];    // h as half2 pairs
__device__ __align__(16) float    g_resid[NN * HC]; // x @ res_w + res_b (fp32)
__device__ __align__(16) float    g_asrc[NN * HHD];
__device__ __align__(16) float    g_adst[NN * HHD];
__device__ __align__(16) float    g_wa[FIN * 8];    // folded att weights
__device__ int g_is64;
__device__ int g_gbase;                             // scan base allocator

// ---------------- helpers ---------------------------------------------------
__device__ __forceinline__ float lrelu(float x) { return x >= 0.f ? x : 0.2f * x; }
__device__ __forceinline__ int clampi(int v) {
    return v < 0 ? 0 : (v >= NN ? NN - 1 : v);
}
__device__ __forceinline__ unsigned f2tf(float f) {
    unsigned u;
    asm("cvt.rna.tf32.f32 %0, %1;" : "=r"(u) : "f"(f));
    return u;
}
__device__ __forceinline__ void mma_tf32(float* d, const unsigned* a,
                                         const unsigned* b) {
    asm volatile(
        "mma.sync.aligned.m16n8k8.row.col.f32.tf32.tf32.f32 "
        "{%0,%1,%2,%3}, {%4,%5,%6,%7}, {%8,%9}, {%0,%1,%2,%3};"
        : "+f"(d[0]), "+f"(d[1]), "+f"(d[2]), "+f"(d[3])
        : "r"(a[0]), "r"(a[1]), "r"(a[2]), "r"(a[3]), "r"(b[0]), "r"(b[1]));
}

// ---------------- zero + detect + fold (one launch) --------------------------
__global__ void k_zerodeg(const int* __restrict__ p, const float* __restrict__ W,
                          const float* __restrict__ att_src,
                          const float* __restrict__ att_dst) {
    int b = blockIdx.x;
    if (b < ZG) {
        int i = b * 256 + threadIdx.x;
        if (i < NN) g_deg[i] = 0;
        if (i == 0) {
            g_gbase = 0;
            int ok64 = 1;
#pragma unroll
            for (int t = 0; t < 8; t++) {
                if (p[2 * t + 1] != 0) ok64 = 0;
                unsigned lo = (unsigned)p[2 * t];
                if (lo >= NN) ok64 = 0;
            }
            g_is64 = ok64;
        }
    } else {
        // fold: warp per output, 8 outputs per block
        int o = (b - ZG) * 8 + (threadIdx.x >> 5);   // 0..511
        int c = threadIdx.x & 31;
        int k = o >> 3, j = o & 7, ph = j & 3;
        const float* att = (j < 4) ? att_src : att_dst;
        float v = W[k * HC + ph * 32 + c] * att[ph * 32 + c];
#pragma unroll
        for (int of = 16; of > 0; of >>= 1)
            v += __shfl_xor_sync(0xffffffffu, v, of);
        if (c == 0) g_wa[o] = v;
    }
}

// ---------------- convert: 4 edges per thread, vectorized --------------------
__global__ void k_convert(const int* __restrict__ p) {
    int t = blockIdx.x * blockDim.x + threadIdx.x;
    int i = t * 4;
    if (i >= EE) return;
    int4 sv, dv;
    if (g_is64) {
        int4 a0 = ((const int4*)p)[i / 2];            // edges i, i+1 (src)
        int4 a1 = ((const int4*)p)[i / 2 + 1];        // edges i+2, i+3
        int4 b0 = ((const int4*)p)[(EE + i) / 2];
        int4 b1 = ((const int4*)p)[(EE + i) / 2 + 1];
        sv = make_int4(a0.x, a0.z, a1.x, a1.z);
        dv = make_int4(b0.x, b0.z, b1.x, b1.z);
    } else {
        sv = ((const int4*)p)[i / 4];
        dv = ((const int4*)p)[(EE + i) / 4];
    }
    sv.x = clampi(sv.x); sv.y = clampi(sv.y); sv.z = clampi(sv.z); sv.w = clampi(sv.w);
    dv.x = clampi(dv.x); dv.y = clampi(dv.y); dv.z = clampi(dv.z); dv.w = clampi(dv.w);
    ((int4*)g_src)[i / 4] = sv;
    ((int4*)g_dst)[i / 4] = dv;
    atomicAdd(&g_deg[dv.x], 1);
    atomicAdd(&g_deg[dv.y], 1);
    atomicAdd(&g_deg[dv.z], 1);
    atomicAdd(&g_deg[dv.w], 1);
}

// ---------------- one-pass scan (atomic base claim) --------------------------
__global__ void __launch_bounds__(SCAN_B) k_scan() {
    __shared__ int wsm[16];
    __shared__ int base;
    const int tid = threadIdx.x, lane = tid & 31, wid = tid >> 5;
    int idx = blockIdx.x * SCAN_B + tid;
    int v = (idx < NN) ? g_deg[idx] : 0;
    int xi = v;
#pragma unroll
    for (int o = 1; o < 32; o <<= 1) {
        int y = __shfl_up_sync(0xffffffffu, xi, o);
        if (lane >= o) xi += y;
    }
    if (lane == 31) wsm[wid] = xi;
    __syncthreads();
    if (wid == 0 && lane < 16) {
        int t = wsm[lane];
#pragma unroll
        for (int o = 1; o < 16; o <<= 1) {
            int y = __shfl_up_sync(0x0000ffffu, t, o);
            if (lane >= o) t += y;
        }
        wsm[lane] = t;
    }
    __syncthreads();
    if (tid == 0) base = atomicAdd(&g_gbase, wsm[15]);
    __syncthreads();
    int woff = (wid == 0) ? 0 : wsm[wid - 1];
    if (idx < NN) {
        int o = base + woff + xi - v;
        g_off[idx] = o;
        g_cursor[idx] = o;
    }
}

// ---------------- scatter: 4 edges per thread --------------------------------
__global__ void k_scatter() {
    int t = blockIdx.x * blockDim.x + threadIdx.x;
    int i = t * 4;
    if (i >= EE) return;
    int4 sv = ((const int4*)g_src)[i / 4];
    int4 dv = ((const int4*)g_dst)[i / 4];
    int p0 = atomicAdd(&g_cursor[dv.x], 1);
    int p1 = atomicAdd(&g_cursor[dv.y], 1);
    int p2 = atomicAdd(&g_cursor[dv.z], 1);
    int p3 = atomicAdd(&g_cursor[dv.w], 1);
    g_csr_src[p0] = sv.x;
    g_csr_src[p1] = sv.y;
    g_csr_src[p2] = sv.z;
    g_csr_src[p3] = sv.w;
}

// ---------------- TF32 tensor-core GEMM + att scalars ------------------------
// [NN x 64] @ [64 x 256]  (cols 0..127 -> g_h2 fp16, 128..255 -> g_resid+res_b)
#define SX 68
#define SW 264
#define GEMM_SMEM ((64 * SX + 64 * SW + 512) * 4)

__global__ void __launch_bounds__(256) k_gemm_mma(
        const float* __restrict__ x, const float* __restrict__ W,
        const float* __restrict__ res_w, const float* __restrict__ res_b) {
    extern __shared__ unsigned sh[];
    unsigned* xs  = sh;                                // 64 x SX (tf32 bits)
    unsigned* ws  = sh + 64 * SX;                      // 64 x SW (tf32 bits)
    float*    was = (float*)(sh + 64 * SX + 64 * SW);  // 512 folded att weights

    const int tid  = threadIdx.x;
    const int row0 = blockIdx.x * 64;

    for (int i = tid; i < FIN * 8; i += 256) was[i] = g_wa[i];
    for (int i = tid; i < FIN * 32; i += 256) {
        int k = i >> 5, q = i & 31;
        float4 w1 = ((const float4*)W)[k * 32 + q];
        float4 w2 = ((const float4*)res_w)[k * 32 + q];
        unsigned* p1 = &ws[k * SW + 4 * q];
        unsigned* p2 = &ws[k * SW + 128 + 4 * q];
        p1[0] = f2tf(w1.x); p1[1] = f2tf(w1.y); p1[2] = f2tf(w1.z); p1[3] = f2tf(w1.w);
        p2[0] = f2tf(w2.x); p2[1] = f2tf(w2.y); p2[2] = f2tf(w2.z); p2[3] = f2tf(w2.w);
    }
    for (int i = tid; i < 64 * 16; i += 256) {
        int r = i >> 4, q = i & 15;
        int row = row0 + r;
        float4 xv = (row < NN) ? ((const float4*)x)[row * 16 + q]
                               : make_float4(0.f, 0.f, 0.f, 0.f);
        unsigned* p = &xs[r * SX + 4 * q];
        p[0] = f2tf(xv.x); p[1] = f2tf(xv.y); p[2] = f2tf(xv.z); p[3] = f2tf(xv.w);
    }
    __syncthreads();

    const int warp = tid >> 5, lane = tid & 31;
    const int mw = warp >> 2, nw = warp & 3;
    const int grp = lane >> 2, tig = lane & 3;
    const int mbase = mw * 32, nbase = nw * 64;

    float acc[2][8][4];
#pragma unroll
    for (int mt = 0; mt < 2; mt++)
#pragma unroll
        for (int nt = 0; nt < 8; nt++)
#pragma unroll
            for (int e = 0; e < 4; e++) acc[mt][nt][e] = 0.f;

#pragma unroll
    for (int kt = 0; kt < 8; kt++) {
        const int k0 = kt * 8;
        unsigned afr[2][4], bfr[8][2];
#pragma unroll
        for (int mt = 0; mt < 2; mt++) {
            int base = (mbase + mt * 16 + grp) * SX + k0 + tig;
            afr[mt][0] = xs[base];
            afr[mt][1] = xs[base + 8 * SX];
            afr[mt][2] = xs[base + 4];
            afr[mt][3] = xs[base + 8 * SX + 4];
        }
#pragma unroll
        for (int nt = 0; nt < 8; nt++) {
            int bb = (k0 + tig) * SW + nbase + nt * 8 + grp;
            bfr[nt][0] = ws[bb];
            bfr[nt][1] = ws[bb + 4 * SW];
        }
#pragma unroll
        for (int mt = 0; mt < 2; mt++)
#pragma unroll
            for (int nt = 0; nt < 8; nt++)
                mma_tf32(acc[mt][nt], afr[mt], bfr[nt]);
    }

    // epilogue: nw 0,1 -> g_h2 (fp16) ; nw 2,3 -> g_resid (fp32, +res_b)
#pragma unroll
    for (int mt = 0; mt < 2; mt++) {
        int r0 = row0 + mbase + mt * 16 + grp;
#pragma unroll
        for (int nt = 0; nt < 8; nt++) {
            int col = nbase + nt * 8 + 2 * tig;
            float v00 = acc[mt][nt][0], v01 = acc[mt][nt][1];
            float v10 = acc[mt][nt][2], v11 = acc[mt][nt][3];
            if (nw < 2) {
                int cp = col >> 1;
                if (r0 < NN)
                    *(__half2*)&g_h2[r0 * 64 + cp] = __floats2half2_rn(v00, v01);
                if (r0 + 8 < NN)
                    *(__half2*)&g_h2[(r0 + 8) * 64 + cp] = __floats2half2_rn(v10, v11);
            } else {
                int cr = col - HC;
                float b0 = res_b[cr], b1 = res_b[cr + 1];
                if (r0 < NN)
                    *(float2*)&g_resid[r0 * HC + cr] = make_float2(v00 + b0, v01 + b1);
                if (r0 + 8 < NN)
                    *(float2*)&g_resid[(r0 + 8) * HC + cr] = make_float2(v10 + b0, v11 + b1);
            }
        }
    }

    // attention scalars from staged x tile (tf32) and folded weights
    {
        const int n = tid >> 2, p = tid & 3;
        float a = 0.f, b = 0.f;
#pragma unroll 16
        for (int k = 0; k < FIN; k++) {
            float xv = __uint_as_float(xs[n * SX + k]);
            a += xv * was[k * 8 + p];
            b += xv * was[k * 8 + 4 + p];
        }
        int node = row0 + n;
        if (node < NN) {
            g_asrc[node * HHD + p] = a;
            g_adst[node * HHD + p] = b;
        }
    }
}

// ---------------- fused aggregate + epilogue ---------------------------------
__global__ void __launch_bounds__(256) k_aggregate(
        const float* __restrict__ bias,
        const float* __restrict__ ln_g, const float* __restrict__ ln_b,
        float* __restrict__ out) {
    int node = (blockIdx.x * blockDim.x + threadIdx.x) >> 5;
    if (node >= NN) return;
    const int l  = threadIdx.x & 31;
    const int hh = l >> 3;

    const float ad = g_adst[node * HHD + hh];
    const int beg = g_off[node];
    const int n   = g_deg[node];

    float4 acc = make_float4(0.f, 0.f, 0.f, 0.f);
    float dsum = 0.f;

    for (int base = 0; base < n; base += 32) {
        int id = (base + l < n) ? g_csr_src[beg + base + l] : 0;
        int cnt = min(32, n - base);
#pragma unroll 4
        for (int j = 0; j < cnt; j++) {
            int s = __shfl_sync(0xffffffffu, id, j);
            float as = g_asrc[s * HHD + hh];
            float ex = __expf(lrelu(as + ad));
            uint2 hb = *(const uint2*)&g_h2[s * 64 + l * 2];
            float2 h01 = __half22float2(*(const __half2*)&hb.x);
            float2 h23 = __half22float2(*(const __half2*)&hb.y);
            acc.x += h01.x * ex; acc.y += h01.y * ex;
            acc.z += h23.x * ex; acc.w += h23.y * ex;
            dsum += ex;
        }
    }

    { // self-loop
        float as = g_asrc[node * HHD + hh];
        float ex = __expf(lrelu(as + ad));
        uint2 hb = *(const uint2*)&g_h2[node * 64 + l * 2];
        float2 h01 = __half22float2(*(const __half2*)&hb.x);
        float2 h23 = __half22float2(*(const __half2*)&hb.y);
        acc.x += h01.x * ex; acc.y += h01.y * ex;
        acc.z += h23.x * ex; acc.w += h23.y * ex;
        dsum += ex;
    }

    float inv = 1.f / dsum;
    float4 bv = *(const float4*)&bias[l * 4];
    float4 rv = *(const float4*)&g_resid[node * HC + l * 4];
    float4 v;
    v.x = acc.x * inv + bv.x;  v.y = acc.y * inv + bv.y;
    v.z = acc.z * inv + bv.z;  v.w = acc.w * inv + bv.w;
    v.x = (v.x > 0.f) ? v.x : expm1f(v.x);
    v.y = (v.y > 0.f) ? v.y : expm1f(v.y);
    v.z = (v.z > 0.f) ? v.z : expm1f(v.z);
    v.w = (v.w > 0.f) ? v.w : expm1f(v.w);
    v.x += rv.x; v.y += rv.y; v.z += rv.z; v.w += rv.w;

    float s1 = v.x + v.y + v.z + v.w;
    float s2 = v.x * v.x + v.y * v.y + v.z * v.z + v.w * v.w;
#pragma unroll
    for (int o = 16; o > 0; o >>= 1) {
        s1 += __shfl_xor_sync(0xffffffffu, s1, o);
        s2 += __shfl_xor_sync(0xffffffffu, s2, o);
    }
    float mu  = s1 * (1.f / 128.f);
    float var = s2 * (1.f / 128.f) - mu * mu;
    float r = rsqrtf(var + 1e-5f);

    float4 gv  = *(const float4*)&ln_g[l * 4];
    float4 bbv = *(const float4*)&ln_b[l * 4];
    float4 o4;
    o4.x = gv.x * (v.x - mu) * r + bbv.x;
    o4.y = gv.y * (v.y - mu) * r + bbv.y;
    o4.z = gv.z * (v.z - mu) * r + bbv.z;
    o4.w = gv.w * (v.w - mu) * r + bbv.w;
    *(float4*)&out[node * HC + l * 4] = o4;
}

// ---------------- launch -----------------------------------------------------
extern "C" void kernel_launch(void* const* d_in, const int* in_sizes, int n_in,
                              void* d_out, int out_size) {
    const float* x       = (const float*)d_in[0];
    const int*   ei      = (const int*)d_in[1];
    const float* W       = (const float*)d_in[2];
    const float* att_src = (const float*)d_in[3];
    const float* att_dst = (const float*)d_in[4];
    const float* bias    = (const float*)d_in[5];
    const float* res_w   = (const float*)d_in[6];
    const float* res_b   = (const float*)d_in[7];
    const float* ln_g    = (const float*)d_in[8];
    const float* ln_b    = (const float*)d_in[9];
    float*       out     = (float*)d_out;

    static bool init = false;
    if (!init) {
        cudaFuncSetAttribute(k_gemm_mma,
                             cudaFuncAttributeMaxDynamicSharedMemorySize, GEMM_SMEM);
        init = true;
    }

    k_zerodeg<<<ZG + FOLD_BLOCKS, 256>>>(ei, W, att_src, att_dst);
    k_convert<<<(EE / 4 + 255) / 256, 256>>>(ei);

    k_gemm_mma<<<(NN + 63) / 64, 256, GEMM_SMEM>>>(x, W, res_w, res_b);

    k_scan<<<SCAN_GRID, SCAN_B>>>();
    k_scatter<<<(EE / 4 + 255) / 256, 256>>>();

    k_aggregate<<<(NN * 32 + 255) / 256, 256>>>(bias, ln_g, ln_b, out);
}